// round 4
// baseline (speedup 1.0000x reference)
#include <cuda_runtime.h>

#define NNODES 200000
#define INDIM  128
#define H1     256
#define HID    16
#define NEG    0.01f

// ---------------- scratch (device globals; no runtime allocation) ----------------
__device__ float g_h   [NNODES * HID];   // MLP output (after 2x leaky_relu)
__device__ float g_hw  [NNODES * HID];   // h @ cw  (per conv layer)
__device__ float g_agg [NNODES * HID];   // aggregation accumulator
__device__ float g_dinv[NNODES];         // deg -> rsqrt(deg)

__device__ __forceinline__ float lrelu(float v) { return v >= 0.f ? v : NEG * v; }

__device__ __forceinline__ int clampN(int i)
{
    i = i < 0 ? 0 : i;
    return i >= NNODES ? NNODES - 1 : i;
}

__device__ __forceinline__ void red_add_v4(float* addr, float a, float b, float c, float d)
{
    asm volatile("red.global.add.v4.f32 [%0], {%1,%2,%3,%4};"
                 :: "l"(addr), "f"(a), "f"(b), "f"(c), "f"(d) : "memory");
}

// ---------------- Kernel 1: fused MLP  h = lrelu(lrelu(x@W1+b1)@W2+b2) ----------------
__global__ __launch_bounds__(256) void mlp_kernel(
    const float* __restrict__ x,
    const float* __restrict__ W1, const float* __restrict__ b1,
    const float* __restrict__ W2, const float* __restrict__ b2)
{
    __shared__ float xs [INDIM * 16];  // transposed: xs[k*16 + n]
    __shared__ float h1s[16 * H1];     // h1s[n*256 + c]

    const int tid = threadIdx.x;
    const int n0  = blockIdx.x * 16;

    for (int i = tid; i < 16 * INDIM; i += 256) {
        int n = i & 15, k = i >> 4;
        xs[i] = x[(n0 + n) * INDIM + k];
    }
    __syncthreads();

    // Stage A: hidden column c for 16 nodes
    {
        const int c = tid;
        float acc[16];
        #pragma unroll
        for (int n = 0; n < 16; n++) acc[n] = 0.f;

        #pragma unroll 4
        for (int k = 0; k < INDIM; k++) {
            const float w = W1[k * H1 + c];
            const float4* xp = (const float4*)(xs + k * 16);
            float4 a = xp[0], b = xp[1], cc = xp[2], d = xp[3];
            acc[ 0] += a.x  * w; acc[ 1] += a.y  * w; acc[ 2] += a.z  * w; acc[ 3] += a.w  * w;
            acc[ 4] += b.x  * w; acc[ 5] += b.y  * w; acc[ 6] += b.z  * w; acc[ 7] += b.w  * w;
            acc[ 8] += cc.x * w; acc[ 9] += cc.y * w; acc[10] += cc.z * w; acc[11] += cc.w * w;
            acc[12] += d.x  * w; acc[13] += d.y  * w; acc[14] += d.z  * w; acc[15] += d.w  * w;
        }
        const float bb = b1[c];
        #pragma unroll
        for (int n = 0; n < 16; n++) h1s[n * H1 + c] = lrelu(acc[n] + bb);
    }
    __syncthreads();

    // Stage B: h2[n][j]
    {
        const int n = tid >> 4, j = tid & 15;
        float s = b2[j];
        #pragma unroll 8
        for (int c = 0; c < H1; c++) s += h1s[n * H1 + c] * W2[c * HID + j];
        g_h[(n0 + n) * HID + j] = lrelu(s);
    }
}

// ---------------- degree / norm kernels ----------------
__global__ void deg_init_kernel()
{
    int i = blockIdx.x * blockDim.x + threadIdx.x;
    if (i < NNODES) g_dinv[i] = 1.0f;  // self-loop
}

__global__ void deg_count_kernel(const int* __restrict__ dst, int E)
{
    int e = blockIdx.x * blockDim.x + threadIdx.x;
    if (e < E) atomicAdd(&g_dinv[clampN(dst[e])], 1.0f);
}

__global__ void deg_rsqrt_kernel()
{
    int i = blockIdx.x * blockDim.x + threadIdx.x;
    if (i < NNODES) g_dinv[i] = rsqrtf(g_dinv[i]);
}

// ---------------- per-conv: hw = (maybe lrelu)(in) @ cw ; agg = cb + self term ----------------
// src_sel: 0 -> read g_h (no leaky), 1 -> read g_agg (apply leaky)
__global__ __launch_bounds__(256) void conv_pre_kernel(
    int src_sel,
    const float* __restrict__ cw, const float* __restrict__ cb)
{
    __shared__ float ws [HID * HID];
    __shared__ float cbs[HID];
    __shared__ float ht [16 * HID];

    const int tid = threadIdx.x;
    const int n0  = blockIdx.x * 16;

    if (tid < HID * HID) ws[tid]  = cw[tid];
    if (tid < HID)       cbs[tid] = cb[tid];
    {
        float v;
        if (src_sel == 0) v = g_h[n0 * HID + tid];
        else              v = lrelu(g_agg[n0 * HID + tid]);
        ht[tid] = v;
    }
    __syncthreads();

    const int n = tid >> 4, j = tid & 15;
    float s = 0.f;
    #pragma unroll
    for (int k = 0; k < HID; k++) s += ht[n * HID + k] * ws[k * HID + j];

    const int gn = n0 + n;
    g_hw[gn * HID + j] = s;
    const float di = g_dinv[gn];
    g_agg[gn * HID + j] = cbs[j] + s * di * di;   // bias + self-loop message
}

// ---------------- per-conv: scatter edge messages ----------------
__global__ __launch_bounds__(256) void conv_edges_kernel(
    const int* __restrict__ src, const int* __restrict__ dst, int E)
{
    int e = blockIdx.x * blockDim.x + threadIdx.x;
    if (e >= E) return;
    const int s = clampN(src[e]);
    const int d = clampN(dst[e]);
    const float nrm = g_dinv[s] * g_dinv[d];

    const float4* hp = (const float4*)(g_hw + (size_t)s * HID);
    float*        ap = g_agg + (size_t)d * HID;
    float4 v0 = hp[0], v1 = hp[1], v2 = hp[2], v3 = hp[3];
    red_add_v4(ap +  0, v0.x*nrm, v0.y*nrm, v0.z*nrm, v0.w*nrm);
    red_add_v4(ap +  4, v1.x*nrm, v1.y*nrm, v1.z*nrm, v1.w*nrm);
    red_add_v4(ap +  8, v2.x*nrm, v2.y*nrm, v2.z*nrm, v2.w*nrm);
    red_add_v4(ap + 12, v3.x*nrm, v3.y*nrm, v3.z*nrm, v3.w*nrm);
}

// ---------------- final: h = lrelu(agg);  out = h @ (pw.sum(1)) + pb.sum() ----------------
__global__ __launch_bounds__(256) void final_kernel(
    const float* __restrict__ pw, const float* __restrict__ pb,
    float* __restrict__ out, long long out_size)
{
    int n = blockIdx.x * blockDim.x + threadIdx.x;
    if (n >= NNODES) return;

    const float4* ap = (const float4*)(g_agg + (size_t)n * HID);
    float h[HID];
    #pragma unroll
    for (int q = 0; q < 4; q++) {
        float4 v = ap[q];
        h[q*4+0] = lrelu(v.x); h[q*4+1] = lrelu(v.y);
        h[q*4+2] = lrelu(v.z); h[q*4+3] = lrelu(v.w);
    }

    float s = pb[0] + pb[1];
    #pragma unroll
    for (int j = 0; j < HID; j++) s += h[j] * (pw[j*2] + pw[j*2+1]);
    out[n] = s;

    if (out_size >= (long long)NNODES * (1 + HID)) {
        float4* op = (float4*)(out + NNODES + (size_t)n * HID);
        #pragma unroll
        for (int q = 0; q < 4; q++)
            op[q] = make_float4(h[q*4+0], h[q*4+1], h[q*4+2], h[q*4+3]);
    }
}

// ---------------- launch: identify inputs by element count (order-robust) ----------------
extern "C" void kernel_launch(void* const* d_in, const int* in_sizes, int n_in,
                              void* d_out, int out_size)
{
    const float *x = 0, *W1 = 0, *b1 = 0, *W2 = 0, *b2 = 0;
    const float *cw0 = 0, *cb0 = 0, *cw1 = 0, *cb1 = 0, *pw = 0, *pb = 0;
    const void  *edges = 0;
    long long    edge_elems = 0;

    int n256 = 0, n16 = 0;
    for (int i = 0; i < n_in; i++) {
        const long long sz = in_sizes[i];
        const void* p = d_in[i];
        switch (sz) {
            case 25600000LL: x  = (const float*)p; break;                 // 200000*128
            case 32768LL:    W1 = (const float*)p; break;                 // 128*256
            case 4096LL:     W2 = (const float*)p; break;                 // 256*16
            case 32LL:       pw = (const float*)p; break;                 // 16*2
            case 2LL:        pb = (const float*)p; break;                 // 2
            case 256LL:                                                   // b1, cw0, cw1 (in order)
                if      (n256 == 0) b1  = (const float*)p;
                else if (n256 == 1) cw0 = (const float*)p;
                else                cw1 = (const float*)p;
                n256++; break;
            case 16LL:                                                    // b2, cb0, cb1 (in order)
                if      (n16 == 0) b2  = (const float*)p;
                else if (n16 == 1) cb0 = (const float*)p;
                else               cb1 = (const float*)p;
                n16++; break;
            default:                                                      // 12,800,000: edge_index
                if (sz > 1000000LL) { edges = p; edge_elems = sz; }
                break;
        }
    }

    const int E = (int)(edge_elems / 2);
    const int* srcp = (const int*)edges;          // edge_index row 0 (int32 under default JAX)
    const int* dstp = (const int*)edges + E;      // edge_index row 1

    float* out = (float*)d_out;

    const int NB_NODES16 = NNODES / 16;           // 12500 (exact)
    const int NB_NODES   = (NNODES + 255) / 256;  // 782
    const int NB_EDGES   = (E + 255) / 256;

    mlp_kernel<<<NB_NODES16, 256>>>(x, W1, b1, W2, b2);

    deg_init_kernel <<<NB_NODES, 256>>>();
    deg_count_kernel<<<NB_EDGES, 256>>>(dstp, E);
    deg_rsqrt_kernel<<<NB_NODES, 256>>>();

    // conv layer 0 (input g_h already has leaky applied)
    conv_pre_kernel  <<<NB_NODES16, 256>>>(0, cw0, cb0);
    conv_edges_kernel<<<NB_EDGES,   256>>>(srcp, dstp, E);

    // conv layer 1 (apply leaky to agg on read)
    conv_pre_kernel  <<<NB_NODES16, 256>>>(1, cw1, cb1);
    conv_edges_kernel<<<NB_EDGES,   256>>>(srcp, dstp, E);

    final_kernel<<<NB_NODES, 256>>>(pw, pb, out, (long long)out_size);
}

// round 5
// speedup vs baseline: 1.4131x; 1.4131x over previous
#include <cuda_runtime.h>

#define NNODES 200000
#define INDIM  128
#define H1     256
#define HID    16
#define NEG    0.01f

// ---------------- scratch (device globals; no runtime allocation) ----------------
__device__ float g_h   [NNODES * HID];   // MLP output (after 2x leaky_relu)
__device__ float g_hw  [NNODES * HID];   // h @ cw  (per conv layer)
__device__ float g_agg [NNODES * HID];   // aggregation accumulator
__device__ float g_dinv[NNODES];         // deg -> rsqrt(deg)

__device__ __forceinline__ float lrelu(float v) { return v >= 0.f ? v : NEG * v; }

__device__ __forceinline__ int clampN(int i)
{
    i = i < 0 ? 0 : i;
    return i >= NNODES ? NNODES - 1 : i;
}

__device__ __forceinline__ void red_add_v4(float* addr, float a, float b, float c, float d)
{
    asm volatile("red.global.add.v4.f32 [%0], {%1,%2,%3,%4};"
                 :: "l"(addr), "f"(a), "f"(b), "f"(c), "f"(d) : "memory");
}

// ---- tf32 helpers -------------------------------------------------------------
__device__ __forceinline__ void split_tf32(float v, unsigned& hi, unsigned& lo)
{
    asm("cvt.rna.tf32.f32 %0, %1;" : "=r"(hi) : "f"(v));
    float r = v - __uint_as_float(hi);
    asm("cvt.rna.tf32.f32 %0, %1;" : "=r"(lo) : "f"(r));
}

#define MMA_TF32(d, a, b)                                                        \
    asm("mma.sync.aligned.m16n8k8.row.col.f32.tf32.tf32.f32 "                    \
        "{%0,%1,%2,%3},{%4,%5,%6,%7},{%8,%9},{%0,%1,%2,%3};"                     \
        : "+f"((d)[0]), "+f"((d)[1]), "+f"((d)[2]), "+f"((d)[3])                 \
        : "r"((a)[0]), "r"((a)[1]), "r"((a)[2]), "r"((a)[3]),                    \
          "r"((b)[0]), "r"((b)[1]))

// ---------------- fused tensor-core MLP ----------------------------------------
// block = 64 nodes, 256 threads (8 warps).
// Stage A: h1[64][256] = lrelu(x@W1+b1) via 3xTF32 mma, W1 staged in 32-row chunks.
// Stage B: h[64][16]   = lrelu(h1@W2+b2) via 3xTF32 mma.
//
// smem (floats): xs  @0      64x132  (8448)   } stage A
//                wsm @8448   32x264  (8448)   }
//                h1s @0      64x260  (16640)    stage B (overwrites xs/wsm)
//                w2s @16896  256x24  (6144)     loaded at start (disjoint)
#define XS  132
#define WS  264
#define HS  260
#define W2S 24
#define SMEM_FLOATS (16896 + 6144)

__global__ __launch_bounds__(256) void mlp_tc_kernel(
    const float* __restrict__ x,
    const float* __restrict__ W1, const float* __restrict__ b1,
    const float* __restrict__ W2, const float* __restrict__ b2)
{
    extern __shared__ float sm[];
    float* xs  = sm;
    float* wsm = sm + 8448;
    float* h1s = sm;
    float* w2s = sm + 16896;

    const int tid  = threadIdx.x;
    const int wid  = tid >> 5;
    const int lane = tid & 31;
    const int g    = lane >> 2;      // group id (row within tile)
    const int t    = lane & 3;       // thread-in-group (k / col pairs)
    const int n0   = blockIdx.x * 64;

    // ---- load x tile [64][128] and W2 [256][16] ----
    {
        const float4* xg = (const float4*)(x + (size_t)n0 * INDIM);
        #pragma unroll
        for (int i = 0; i < 8; i++) {
            int lin = i * 256 + tid;                 // 2048 float4s
            int row = lin >> 5, c4 = (lin & 31) << 2;
            float4 v = xg[lin];
            *(float4*)(xs + row * XS + c4) = v;
        }
        const float4* wg = (const float4*)W2;
        #pragma unroll
        for (int i = 0; i < 4; i++) {
            int lin = i * 256 + tid;                 // 1024 float4s
            int row = lin >> 2, c4 = (lin & 3) << 2;
            float4 v = wg[lin];
            *(float4*)(w2s + row * W2S + c4) = v;
        }
    }

    // ---- stage A: warp (wm, wn): rows wm*32..+32, cols wn*64..+64 ----
    const int wm = wid >> 2;
    const int wn = wid & 3;
    float acc[2][8][4];
    #pragma unroll
    for (int mt = 0; mt < 2; mt++)
        #pragma unroll
        for (int nt = 0; nt < 8; nt++)
            #pragma unroll
            for (int r = 0; r < 4; r++) acc[mt][nt][r] = 0.f;

    for (int k0 = 0; k0 < INDIM; k0 += 32) {
        // stage W1 chunk [32][256] into wsm
        __syncthreads();
        {
            const float4* wg = (const float4*)(W1 + (size_t)k0 * H1);
            #pragma unroll
            for (int i = 0; i < 8; i++) {
                int lin = i * 256 + tid;             // 2048 float4s
                int row = lin >> 6, c4 = (lin & 63) << 2;
                float4 v = wg[lin];
                *(float4*)(wsm + row * WS + c4) = v;
            }
        }
        __syncthreads();

        #pragma unroll
        for (int ks = 0; ks < 32; ks += 8) {
            // A fragments (both m-tiles), split hi/lo
            unsigned ahi[2][4], alo[2][4];
            #pragma unroll
            for (int mt = 0; mt < 2; mt++) {
                int rb = wm * 32 + mt * 16;
                float a0 = xs[(rb + g)     * XS + k0 + ks + t];
                float a1 = xs[(rb + g + 8) * XS + k0 + ks + t];
                float a2 = xs[(rb + g)     * XS + k0 + ks + t + 4];
                float a3 = xs[(rb + g + 8) * XS + k0 + ks + t + 4];
                split_tf32(a0, ahi[mt][0], alo[mt][0]);
                split_tf32(a1, ahi[mt][1], alo[mt][1]);
                split_tf32(a2, ahi[mt][2], alo[mt][2]);
                split_tf32(a3, ahi[mt][3], alo[mt][3]);
            }
            #pragma unroll
            for (int nt = 0; nt < 8; nt++) {
                int cb = wn * 64 + nt * 8;
                float b0f = wsm[(ks + t)     * WS + cb + g];
                float b1f = wsm[(ks + t + 4) * WS + cb + g];
                unsigned bhi[2], blo[2];
                split_tf32(b0f, bhi[0], blo[0]);
                split_tf32(b1f, bhi[1], blo[1]);
                #pragma unroll
                for (int mt = 0; mt < 2; mt++) {
                    MMA_TF32(acc[mt][nt], ahi[mt], bhi);
                    MMA_TF32(acc[mt][nt], ahi[mt], blo);
                    MMA_TF32(acc[mt][nt], alo[mt], bhi);
                }
            }
        }
    }
    __syncthreads();   // done reading xs/wsm; safe to overwrite with h1s

    // epilogue A: bias + leaky -> h1s
    #pragma unroll
    for (int mt = 0; mt < 2; mt++) {
        int rb = wm * 32 + mt * 16;
        #pragma unroll
        for (int nt = 0; nt < 8; nt++) {
            int cb = wn * 64 + nt * 8 + t * 2;
            float bb0 = b1[cb], bb1 = b1[cb + 1];
            h1s[(rb + g)     * HS + cb    ] = lrelu(acc[mt][nt][0] + bb0);
            h1s[(rb + g)     * HS + cb + 1] = lrelu(acc[mt][nt][1] + bb1);
            h1s[(rb + g + 8) * HS + cb    ] = lrelu(acc[mt][nt][2] + bb0);
            h1s[(rb + g + 8) * HS + cb + 1] = lrelu(acc[mt][nt][3] + bb1);
        }
    }
    __syncthreads();

    // ---- stage B: warp -> (mt2 rows 16, nt2 cols 8); K = 256 ----
    {
        const int mt2 = wid >> 1;           // 0..3 -> rows mt2*16
        const int nt2 = wid & 1;            // 0..1 -> cols nt2*8
        const int rb  = mt2 * 16;
        const int cb  = nt2 * 8;
        float d[4] = {0.f, 0.f, 0.f, 0.f};

        #pragma unroll 4
        for (int k = 0; k < H1; k += 8) {
            float a0 = h1s[(rb + g)     * HS + k + t];
            float a1 = h1s[(rb + g + 8) * HS + k + t];
            float a2 = h1s[(rb + g)     * HS + k + t + 4];
            float a3 = h1s[(rb + g + 8) * HS + k + t + 4];
            unsigned ahi[4], alo[4];
            split_tf32(a0, ahi[0], alo[0]);
            split_tf32(a1, ahi[1], alo[1]);
            split_tf32(a2, ahi[2], alo[2]);
            split_tf32(a3, ahi[3], alo[3]);
            float b0f = w2s[(k + t)     * W2S + cb + g];
            float b1f = w2s[(k + t + 4) * W2S + cb + g];
            unsigned bhi[2], blo[2];
            split_tf32(b0f, bhi[0], blo[0]);
            split_tf32(b1f, bhi[1], blo[1]);
            MMA_TF32(d, ahi, bhi);
            MMA_TF32(d, ahi, blo);
            MMA_TF32(d, alo, bhi);
        }

        int col = cb + t * 2;
        float bb0 = b2[col], bb1 = b2[col + 1];
        g_h[(size_t)(n0 + rb + g)     * HID + col    ] = lrelu(d[0] + bb0);
        g_h[(size_t)(n0 + rb + g)     * HID + col + 1] = lrelu(d[1] + bb1);
        g_h[(size_t)(n0 + rb + g + 8) * HID + col    ] = lrelu(d[2] + bb0);
        g_h[(size_t)(n0 + rb + g + 8) * HID + col + 1] = lrelu(d[3] + bb1);
    }
}

// ---------------- degree / norm kernels ----------------
__global__ void deg_init_kernel()
{
    int i = blockIdx.x * blockDim.x + threadIdx.x;
    if (i < NNODES) g_dinv[i] = 1.0f;  // self-loop
}

__global__ void deg_count_kernel(const int* __restrict__ dst, int E)
{
    int e = blockIdx.x * blockDim.x + threadIdx.x;
    if (e < E) atomicAdd(&g_dinv[clampN(dst[e])], 1.0f);
}

__global__ void deg_rsqrt_kernel()
{
    int i = blockIdx.x * blockDim.x + threadIdx.x;
    if (i < NNODES) g_dinv[i] = rsqrtf(g_dinv[i]);
}

// ---------------- per-conv: hw = (maybe lrelu)(in) @ cw ; agg = cb + self term ----------------
__global__ __launch_bounds__(256) void conv_pre_kernel(
    int src_sel,
    const float* __restrict__ cw, const float* __restrict__ cb)
{
    __shared__ float ws [HID * HID];
    __shared__ float cbs[HID];
    __shared__ float ht [16 * HID];

    const int tid = threadIdx.x;
    const int n0  = blockIdx.x * 16;

    if (tid < HID * HID) ws[tid]  = cw[tid];
    if (tid < HID)       cbs[tid] = cb[tid];
    {
        float v;
        if (src_sel == 0) v = g_h[n0 * HID + tid];
        else              v = lrelu(g_agg[n0 * HID + tid]);
        ht[tid] = v;
    }
    __syncthreads();

    const int n = tid >> 4, j = tid & 15;
    float s = 0.f;
    #pragma unroll
    for (int k = 0; k < HID; k++) s += ht[n * HID + k] * ws[k * HID + j];

    const int gn = n0 + n;
    g_hw[gn * HID + j] = s;
    const float di = g_dinv[gn];
    g_agg[gn * HID + j] = cbs[j] + s * di * di;   // bias + self-loop message
}

// ---------------- per-conv: scatter edge messages ----------------
__global__ __launch_bounds__(256) void conv_edges_kernel(
    const int* __restrict__ src, const int* __restrict__ dst, int E)
{
    int e = blockIdx.x * blockDim.x + threadIdx.x;
    if (e >= E) return;
    const int s = clampN(src[e]);
    const int d = clampN(dst[e]);
    const float nrm = g_dinv[s] * g_dinv[d];

    const float4* hp = (const float4*)(g_hw + (size_t)s * HID);
    float*        ap = g_agg + (size_t)d * HID;
    float4 v0 = hp[0], v1 = hp[1], v2 = hp[2], v3 = hp[3];
    red_add_v4(ap +  0, v0.x*nrm, v0.y*nrm, v0.z*nrm, v0.w*nrm);
    red_add_v4(ap +  4, v1.x*nrm, v1.y*nrm, v1.z*nrm, v1.w*nrm);
    red_add_v4(ap +  8, v2.x*nrm, v2.y*nrm, v2.z*nrm, v2.w*nrm);
    red_add_v4(ap + 12, v3.x*nrm, v3.y*nrm, v3.z*nrm, v3.w*nrm);
}

// ---------------- final: h = lrelu(agg);  out = h @ (pw.sum(1)) + pb.sum() ----------------
__global__ __launch_bounds__(256) void final_kernel(
    const float* __restrict__ pw, const float* __restrict__ pb,
    float* __restrict__ out, long long out_size)
{
    int n = blockIdx.x * blockDim.x + threadIdx.x;
    if (n >= NNODES) return;

    const float4* ap = (const float4*)(g_agg + (size_t)n * HID);
    float h[HID];
    #pragma unroll
    for (int q = 0; q < 4; q++) {
        float4 v = ap[q];
        h[q*4+0] = lrelu(v.x); h[q*4+1] = lrelu(v.y);
        h[q*4+2] = lrelu(v.z); h[q*4+3] = lrelu(v.w);
    }

    float s = pb[0] + pb[1];
    #pragma unroll
    for (int j = 0; j < HID; j++) s += h[j] * (pw[j*2] + pw[j*2+1]);
    out[n] = s;

    if (out_size >= (long long)NNODES * (1 + HID)) {
        float4* op = (float4*)(out + NNODES + (size_t)n * HID);
        #pragma unroll
        for (int q = 0; q < 4; q++)
            op[q] = make_float4(h[q*4+0], h[q*4+1], h[q*4+2], h[q*4+3]);
    }
}

// ---------------- launch: identify inputs by element count (order-robust) ----------------
extern "C" void kernel_launch(void* const* d_in, const int* in_sizes, int n_in,
                              void* d_out, int out_size)
{
    const float *x = 0, *W1 = 0, *b1 = 0, *W2 = 0, *b2 = 0;
    const float *cw0 = 0, *cb0 = 0, *cw1 = 0, *cb1 = 0, *pw = 0, *pb = 0;
    const void  *edges = 0;
    long long    edge_elems = 0;

    int n256 = 0, n16 = 0;
    for (int i = 0; i < n_in; i++) {
        const long long sz = in_sizes[i];
        const void* p = d_in[i];
        switch (sz) {
            case 25600000LL: x  = (const float*)p; break;                 // 200000*128
            case 32768LL:    W1 = (const float*)p; break;                 // 128*256
            case 4096LL:     W2 = (const float*)p; break;                 // 256*16
            case 32LL:       pw = (const float*)p; break;                 // 16*2
            case 2LL:        pb = (const float*)p; break;                 // 2
            case 256LL:                                                   // b1, cw0, cw1 (in order)
                if      (n256 == 0) b1  = (const float*)p;
                else if (n256 == 1) cw0 = (const float*)p;
                else                cw1 = (const float*)p;
                n256++; break;
            case 16LL:                                                    // b2, cb0, cb1 (in order)
                if      (n16 == 0) b2  = (const float*)p;
                else if (n16 == 1) cb0 = (const float*)p;
                else               cb1 = (const float*)p;
                n16++; break;
            default:                                                      // 12,800,000: edge_index
                if (sz > 1000000LL) { edges = p; edge_elems = sz; }
                break;
        }
    }

    const int E = (int)(edge_elems / 2);
    const int* srcp = (const int*)edges;
    const int* dstp = (const int*)edges + E;

    float* out = (float*)d_out;

    const int NB_NODES16 = NNODES / 16;
    const int NB_NODES   = (NNODES + 255) / 256;
    const int NB_EDGES   = (E + 255) / 256;

    static int smem_set = 0;
    if (!smem_set) {
        cudaFuncSetAttribute(mlp_tc_kernel,
                             cudaFuncAttributeMaxDynamicSharedMemorySize,
                             SMEM_FLOATS * 4);
        smem_set = 1;
    }

    mlp_tc_kernel<<<NNODES / 64, 256, SMEM_FLOATS * 4>>>(x, W1, b1, W2, b2);

    deg_init_kernel <<<NB_NODES, 256>>>();
    deg_count_kernel<<<NB_EDGES, 256>>>(dstp, E);
    deg_rsqrt_kernel<<<NB_NODES, 256>>>();

    conv_pre_kernel  <<<NB_NODES16, 256>>>(0, cw0, cb0);
    conv_edges_kernel<<<NB_EDGES,   256>>>(srcp, dstp, E);

    conv_pre_kernel  <<<NB_NODES16, 256>>>(1, cw1, cb1);
    conv_edges_kernel<<<NB_EDGES,   256>>>(srcp, dstp, E);

    final_kernel<<<NB_NODES, 256>>>(pw, pb, out, (long long)out_size);
}

// round 6
// speedup vs baseline: 1.9575x; 1.3853x over previous
#include <cuda_runtime.h>

#define NNODES 200000
#define INDIM  128
#define H1     256
#define HID    16
#define NEG    0.01f
#define EMAX   6400000
#define NB_SCAN 782          // ceil(200000/256)

// ---------------- scratch (device globals; no runtime allocation) ----------------
__device__ float g_h   [NNODES * HID];   // MLP output
__device__ float g_hw  [NNODES * HID];   // (h @ cw) * dinv  (per conv layer)
__device__ float g_agg [NNODES * HID];   // aggregation result
__device__ float g_dinv[NNODES];
__device__ int   g_cnt [NNODES];         // in-degree (no self loop)
__device__ int   g_off [NNODES];         // CSR row offsets (exclusive)
__device__ int   g_cur [NNODES];         // scatter cursors
__device__ int   g_srcs[EMAX];           // CSR col: src node per incoming edge
__device__ int   g_bsum[1024];           // scan partials
__device__ int   g_boff[1024];

__device__ __forceinline__ float lrelu(float v) { return v >= 0.f ? v : NEG * v; }

__device__ __forceinline__ int clampN(int i)
{
    i = i < 0 ? 0 : i;
    return i >= NNODES ? NNODES - 1 : i;
}

// ---- tf32 helpers -------------------------------------------------------------
__device__ __forceinline__ void split_tf32(float v, unsigned& hi, unsigned& lo)
{
    asm("cvt.rna.tf32.f32 %0, %1;" : "=r"(hi) : "f"(v));
    float r = v - __uint_as_float(hi);
    asm("cvt.rna.tf32.f32 %0, %1;" : "=r"(lo) : "f"(r));
}

#define MMA_TF32(d, a, b)                                                        \
    asm("mma.sync.aligned.m16n8k8.row.col.f32.tf32.tf32.f32 "                    \
        "{%0,%1,%2,%3},{%4,%5,%6,%7},{%8,%9},{%0,%1,%2,%3};"                     \
        : "+f"((d)[0]), "+f"((d)[1]), "+f"((d)[2]), "+f"((d)[3])                 \
        : "r"((a)[0]), "r"((a)[1]), "r"((a)[2]), "r"((a)[3]),                    \
          "r"((b)[0]), "r"((b)[1]))

// ---------------- fused tensor-core MLP (unchanged from R5) ----------------------
#define XS  132
#define WS  264
#define HS  260
#define W2S 24
#define SMEM_FLOATS (16896 + 6144)

__global__ __launch_bounds__(256) void mlp_tc_kernel(
    const float* __restrict__ x,
    const float* __restrict__ W1, const float* __restrict__ b1,
    const float* __restrict__ W2, const float* __restrict__ b2)
{
    extern __shared__ float sm[];
    float* xs  = sm;
    float* wsm = sm + 8448;
    float* h1s = sm;
    float* w2s = sm + 16896;

    const int tid  = threadIdx.x;
    const int wid  = tid >> 5;
    const int lane = tid & 31;
    const int g    = lane >> 2;
    const int t    = lane & 3;
    const int n0   = blockIdx.x * 64;

    {
        const float4* xg = (const float4*)(x + (size_t)n0 * INDIM);
        #pragma unroll
        for (int i = 0; i < 8; i++) {
            int lin = i * 256 + tid;
            int row = lin >> 5, c4 = (lin & 31) << 2;
            float4 v = xg[lin];
            *(float4*)(xs + row * XS + c4) = v;
        }
        const float4* wg = (const float4*)W2;
        #pragma unroll
        for (int i = 0; i < 4; i++) {
            int lin = i * 256 + tid;
            int row = lin >> 2, c4 = (lin & 3) << 2;
            float4 v = wg[lin];
            *(float4*)(w2s + row * W2S + c4) = v;
        }
    }

    const int wm = wid >> 2;
    const int wn = wid & 3;
    float acc[2][8][4];
    #pragma unroll
    for (int mt = 0; mt < 2; mt++)
        #pragma unroll
        for (int nt = 0; nt < 8; nt++)
            #pragma unroll
            for (int r = 0; r < 4; r++) acc[mt][nt][r] = 0.f;

    for (int k0 = 0; k0 < INDIM; k0 += 32) {
        __syncthreads();
        {
            const float4* wg = (const float4*)(W1 + (size_t)k0 * H1);
            #pragma unroll
            for (int i = 0; i < 8; i++) {
                int lin = i * 256 + tid;
                int row = lin >> 6, c4 = (lin & 63) << 2;
                float4 v = wg[lin];
                *(float4*)(wsm + row * WS + c4) = v;
            }
        }
        __syncthreads();

        #pragma unroll
        for (int ks = 0; ks < 32; ks += 8) {
            unsigned ahi[2][4], alo[2][4];
            #pragma unroll
            for (int mt = 0; mt < 2; mt++) {
                int rb = wm * 32 + mt * 16;
                float a0 = xs[(rb + g)     * XS + k0 + ks + t];
                float a1 = xs[(rb + g + 8) * XS + k0 + ks + t];
                float a2 = xs[(rb + g)     * XS + k0 + ks + t + 4];
                float a3 = xs[(rb + g + 8) * XS + k0 + ks + t + 4];
                split_tf32(a0, ahi[mt][0], alo[mt][0]);
                split_tf32(a1, ahi[mt][1], alo[mt][1]);
                split_tf32(a2, ahi[mt][2], alo[mt][2]);
                split_tf32(a3, ahi[mt][3], alo[mt][3]);
            }
            #pragma unroll
            for (int nt = 0; nt < 8; nt++) {
                int cb = wn * 64 + nt * 8;
                float b0f = wsm[(ks + t)     * WS + cb + g];
                float b1f = wsm[(ks + t + 4) * WS + cb + g];
                unsigned bhi[2], blo[2];
                split_tf32(b0f, bhi[0], blo[0]);
                split_tf32(b1f, bhi[1], blo[1]);
                #pragma unroll
                for (int mt = 0; mt < 2; mt++) {
                    MMA_TF32(acc[mt][nt], ahi[mt], bhi);
                    MMA_TF32(acc[mt][nt], ahi[mt], blo);
                    MMA_TF32(acc[mt][nt], alo[mt], bhi);
                }
            }
        }
    }
    __syncthreads();

    #pragma unroll
    for (int mt = 0; mt < 2; mt++) {
        int rb = wm * 32 + mt * 16;
        #pragma unroll
        for (int nt = 0; nt < 8; nt++) {
            int cb = wn * 64 + nt * 8 + t * 2;
            float bb0 = b1[cb], bb1 = b1[cb + 1];
            h1s[(rb + g)     * HS + cb    ] = lrelu(acc[mt][nt][0] + bb0);
            h1s[(rb + g)     * HS + cb + 1] = lrelu(acc[mt][nt][1] + bb1);
            h1s[(rb + g + 8) * HS + cb    ] = lrelu(acc[mt][nt][2] + bb0);
            h1s[(rb + g + 8) * HS + cb + 1] = lrelu(acc[mt][nt][3] + bb1);
        }
    }
    __syncthreads();

    {
        const int mt2 = wid >> 1;
        const int nt2 = wid & 1;
        const int rb  = mt2 * 16;
        const int cb  = nt2 * 8;
        float d[4] = {0.f, 0.f, 0.f, 0.f};

        #pragma unroll 4
        for (int k = 0; k < H1; k += 8) {
            float a0 = h1s[(rb + g)     * HS + k + t];
            float a1 = h1s[(rb + g + 8) * HS + k + t];
            float a2 = h1s[(rb + g)     * HS + k + t + 4];
            float a3 = h1s[(rb + g + 8) * HS + k + t + 4];
            unsigned ahi[4], alo[4];
            split_tf32(a0, ahi[0], alo[0]);
            split_tf32(a1, ahi[1], alo[1]);
            split_tf32(a2, ahi[2], alo[2]);
            split_tf32(a3, ahi[3], alo[3]);
            float b0f = w2s[(k + t)     * W2S + cb + g];
            float b1f = w2s[(k + t + 4) * W2S + cb + g];
            unsigned bhi[2], blo[2];
            split_tf32(b0f, bhi[0], blo[0]);
            split_tf32(b1f, bhi[1], blo[1]);
            MMA_TF32(d, ahi, bhi);
            MMA_TF32(d, ahi, blo);
            MMA_TF32(d, alo, bhi);
        }

        int col = cb + t * 2;
        float bb0 = b2[col], bb1 = b2[col + 1];
        g_h[(size_t)(n0 + rb + g)     * HID + col    ] = lrelu(d[0] + bb0);
        g_h[(size_t)(n0 + rb + g)     * HID + col + 1] = lrelu(d[1] + bb1);
        g_h[(size_t)(n0 + rb + g + 8) * HID + col    ] = lrelu(d[2] + bb0);
        g_h[(size_t)(n0 + rb + g + 8) * HID + col + 1] = lrelu(d[3] + bb1);
    }
}

// ---------------- CSR build --------------------------------------------------
__global__ void zero_cnt_kernel()
{
    int i = blockIdx.x * blockDim.x + threadIdx.x;
    if (i < NNODES) g_cnt[i] = 0;
}

__global__ void deg_count_kernel(const int* __restrict__ dst, int E)
{
    int e = blockIdx.x * blockDim.x + threadIdx.x;
    if (e < E) atomicAdd(&g_cnt[clampN(dst[e])], 1);
}

// scan A: per-block sums of g_cnt
__global__ __launch_bounds__(256) void scanA_kernel()
{
    __shared__ int s[256];
    int i = blockIdx.x * 256 + threadIdx.x;
    s[threadIdx.x] = (i < NNODES) ? g_cnt[i] : 0;
    __syncthreads();
    for (int o = 128; o > 0; o >>= 1) {
        if (threadIdx.x < o) s[threadIdx.x] += s[threadIdx.x + o];
        __syncthreads();
    }
    if (threadIdx.x == 0) g_bsum[blockIdx.x] = s[0];
}

// scan B: exclusive scan of NB_SCAN block sums (single block, 1024 threads)
__global__ __launch_bounds__(1024) void scanB_kernel()
{
    __shared__ int s[1024];
    int tid = threadIdx.x;
    int v = (tid < NB_SCAN) ? g_bsum[tid] : 0;
    s[tid] = v;
    __syncthreads();
    for (int o = 1; o < 1024; o <<= 1) {
        int t = (tid >= o) ? s[tid - o] : 0;
        __syncthreads();
        s[tid] += t;
        __syncthreads();
    }
    if (tid < NB_SCAN) g_boff[tid] = s[tid] - v;   // exclusive
}

// scan C: per-element offsets, init cursors, dinv
__global__ __launch_bounds__(256) void scanC_kernel()
{
    __shared__ int s[256];
    int tid = threadIdx.x;
    int i = blockIdx.x * 256 + tid;
    int c = (i < NNODES) ? g_cnt[i] : 0;
    s[tid] = c;
    __syncthreads();
    for (int o = 1; o < 256; o <<= 1) {
        int t = (tid >= o) ? s[tid - o] : 0;
        __syncthreads();
        s[tid] += t;
        __syncthreads();
    }
    if (i < NNODES) {
        int off = g_boff[blockIdx.x] + s[tid] - c;   // exclusive
        g_off[i] = off;
        g_cur[i] = off;
        g_dinv[i] = rsqrtf((float)(c + 1));          // +1 self loop
    }
}

__global__ void scatter_kernel(const int* __restrict__ src, const int* __restrict__ dst, int E)
{
    int e = blockIdx.x * blockDim.x + threadIdx.x;
    if (e >= E) return;
    const int s = clampN(src[e]);
    const int d = clampN(dst[e]);
    int pos = atomicAdd(&g_cur[d], 1);
    g_srcs[pos] = s;
}

// ---------------- per-conv: g_hw = ((maybe lrelu)(in) @ cw) * dinv --------------
__global__ __launch_bounds__(256) void conv_pre_kernel(
    int src_sel,
    const float* __restrict__ cw)
{
    __shared__ float ws[HID * HID];
    __shared__ float ht[16 * HID];

    const int tid = threadIdx.x;
    const int n0  = blockIdx.x * 16;

    if (tid < HID * HID) ws[tid] = cw[tid];
    {
        float v;
        if (src_sel == 0) v = g_h[n0 * HID + tid];
        else              v = lrelu(g_agg[n0 * HID + tid]);
        ht[tid] = v;
    }
    __syncthreads();

    const int n = tid >> 4, j = tid & 15;
    float s = 0.f;
    #pragma unroll
    for (int k = 0; k < HID; k++) s += ht[n * HID + k] * ws[k * HID + j];

    const int gn = n0 + n;
    g_hw[gn * HID + j] = s * g_dinv[gn];
}

// ---------------- aggregation: warp per node, gather from CSR -------------------
// agg[n] = cb + dinv[n] * ( sum_{s in srcs(n)} g_hw[s] + g_hw[n] )
__global__ __launch_bounds__(256) void agg_kernel(const float* __restrict__ cb)
{
    const int wid  = threadIdx.x >> 5;
    const int lane = threadIdx.x & 31;
    const int n    = blockIdx.x * 8 + wid;
    if (n >= NNODES) return;

    const int q  = lane & 3;       // feature quad
    const int es = lane >> 2;      // edge sub-slot 0..7

    const int beg = g_off[n];
    const int end = beg + g_cnt[n];

    float4 acc = make_float4(0.f, 0.f, 0.f, 0.f);

    for (int i = beg; i < end; i += 8) {
        int sl = -1;
        if (lane < 8 && i + lane < end) sl = g_srcs[i + lane];
        int s = __shfl_sync(0xffffffffu, sl, es);
        if (s >= 0) {
            const float4 v = *(const float4*)(g_hw + (size_t)s * HID + q * 4);
            acc.x += v.x; acc.y += v.y; acc.z += v.z; acc.w += v.w;
        }
    }

    // butterfly-reduce across es (lane bits 2..4)
    #pragma unroll
    for (int o = 16; o >= 4; o >>= 1) {
        acc.x += __shfl_xor_sync(0xffffffffu, acc.x, o);
        acc.y += __shfl_xor_sync(0xffffffffu, acc.y, o);
        acc.z += __shfl_xor_sync(0xffffffffu, acc.z, o);
        acc.w += __shfl_xor_sync(0xffffffffu, acc.w, o);
    }

    if (lane < 4) {
        const float4 hwn = *(const float4*)(g_hw + (size_t)n * HID + q * 4);
        const float  di  = g_dinv[n];
        const float4 cb4 = __ldg((const float4*)cb + q);
        float4 r;
        r.x = cb4.x + di * (acc.x + hwn.x);
        r.y = cb4.y + di * (acc.y + hwn.y);
        r.z = cb4.z + di * (acc.z + hwn.z);
        r.w = cb4.w + di * (acc.w + hwn.w);
        *(float4*)(g_agg + (size_t)n * HID + q * 4) = r;
    }
}

// ---------------- final: h = lrelu(agg);  out = h @ (pw.sum(1)) + pb.sum() ------
__global__ __launch_bounds__(256) void final_kernel(
    const float* __restrict__ pw, const float* __restrict__ pb,
    float* __restrict__ out, long long out_size)
{
    int n = blockIdx.x * blockDim.x + threadIdx.x;
    if (n >= NNODES) return;

    const float4* ap = (const float4*)(g_agg + (size_t)n * HID);
    float h[HID];
    #pragma unroll
    for (int q = 0; q < 4; q++) {
        float4 v = ap[q];
        h[q*4+0] = lrelu(v.x); h[q*4+1] = lrelu(v.y);
        h[q*4+2] = lrelu(v.z); h[q*4+3] = lrelu(v.w);
    }

    float s = pb[0] + pb[1];
    #pragma unroll
    for (int j = 0; j < HID; j++) s += h[j] * (pw[j*2] + pw[j*2+1]);
    out[n] = s;

    if (out_size >= (long long)NNODES * (1 + HID)) {
        float4* op = (float4*)(out + NNODES + (size_t)n * HID);
        #pragma unroll
        for (int q = 0; q < 4; q++)
            op[q] = make_float4(h[q*4+0], h[q*4+1], h[q*4+2], h[q*4+3]);
    }
}

// ---------------- launch: identify inputs by element count ----------------------
extern "C" void kernel_launch(void* const* d_in, const int* in_sizes, int n_in,
                              void* d_out, int out_size)
{
    const float *x = 0, *W1 = 0, *b1 = 0, *W2 = 0, *b2 = 0;
    const float *cw0 = 0, *cb0 = 0, *cw1 = 0, *cb1 = 0, *pw = 0, *pb = 0;
    const void  *edges = 0;
    long long    edge_elems = 0;

    int n256 = 0, n16 = 0;
    for (int i = 0; i < n_in; i++) {
        const long long sz = in_sizes[i];
        const void* p = d_in[i];
        switch (sz) {
            case 25600000LL: x  = (const float*)p; break;
            case 32768LL:    W1 = (const float*)p; break;
            case 4096LL:     W2 = (const float*)p; break;
            case 32LL:       pw = (const float*)p; break;
            case 2LL:        pb = (const float*)p; break;
            case 256LL:
                if      (n256 == 0) b1  = (const float*)p;
                else if (n256 == 1) cw0 = (const float*)p;
                else                cw1 = (const float*)p;
                n256++; break;
            case 16LL:
                if      (n16 == 0) b2  = (const float*)p;
                else if (n16 == 1) cb0 = (const float*)p;
                else               cb1 = (const float*)p;
                n16++; break;
            default:
                if (sz > 1000000LL) { edges = p; edge_elems = sz; }
                break;
        }
    }

    int E = (int)(edge_elems / 2);
    if (E > EMAX) E = EMAX;
    const int* srcp = (const int*)edges;
    const int* dstp = (const int*)edges + E;

    float* out = (float*)d_out;

    const int NB_NODES16 = NNODES / 16;
    const int NB_NODES   = (NNODES + 255) / 256;
    const int NB_EDGES   = (E + 255) / 256;
    const int NB_AGG     = (NNODES + 7) / 8;

    static int smem_set = 0;
    if (!smem_set) {
        cudaFuncSetAttribute(mlp_tc_kernel,
                             cudaFuncAttributeMaxDynamicSharedMemorySize,
                             SMEM_FLOATS * 4);
        smem_set = 1;
    }

    mlp_tc_kernel<<<NNODES / 64, 256, SMEM_FLOATS * 4>>>(x, W1, b1, W2, b2);

    // CSR build (once, reused by both conv layers)
    zero_cnt_kernel <<<NB_NODES, 256>>>();
    deg_count_kernel<<<NB_EDGES, 256>>>(dstp, E);
    scanA_kernel    <<<NB_SCAN, 256>>>();
    scanB_kernel    <<<1, 1024>>>();
    scanC_kernel    <<<NB_SCAN, 256>>>();
    scatter_kernel  <<<NB_EDGES, 256>>>(srcp, dstp, E);

    // conv layer 0
    conv_pre_kernel<<<NB_NODES16, 256>>>(0, cw0);
    agg_kernel     <<<NB_AGG, 256>>>(cb0);

    // conv layer 1
    conv_pre_kernel<<<NB_NODES16, 256>>>(1, cw1);
    agg_kernel     <<<NB_AGG, 256>>>(cb1);

    final_kernel<<<NB_NODES, 256>>>(pw, pb, out, (long long)out_size);
}

// round 7
// speedup vs baseline: 2.0181x; 1.0310x over previous
#include <cuda_runtime.h>

#define NNODES 200000
#define INDIM  128
#define H1     256
#define HID    16
#define NEG    0.01f
#define EMAX   6400000
#define NB_SCAN 782          // ceil(200000/256)

// ---------------- scratch (device globals; no runtime allocation) ----------------
__device__ float g_h   [NNODES * HID];   // MLP output
__device__ float g_hw  [NNODES * HID];   // (h @ cw) * dinv  (per conv layer)
__device__ float g_agg [NNODES * HID];   // aggregation result
__device__ float g_dinv[NNODES];
__device__ int   g_cnt [NNODES];         // in-degree (no self loop)
__device__ int   g_off [NNODES];         // CSR row offsets (exclusive)
__device__ int   g_cur [NNODES];         // scatter cursors
__device__ int   g_srcs[EMAX];           // CSR col: src node per incoming edge
__device__ int   g_bsum[1024];           // scan partials
__device__ int   g_boff[1024];

__device__ __forceinline__ float lrelu(float v) { return v >= 0.f ? v : NEG * v; }

__device__ __forceinline__ int clampN(int i)
{
    i = i < 0 ? 0 : i;
    return i >= NNODES ? NNODES - 1 : i;
}

// ---- tf32 helpers -------------------------------------------------------------
__device__ __forceinline__ void split_tf32(float v, unsigned& hi, unsigned& lo)
{
    asm("cvt.rna.tf32.f32 %0, %1;" : "=r"(hi) : "f"(v));
    float r = v - __uint_as_float(hi);
    asm("cvt.rna.tf32.f32 %0, %1;" : "=r"(lo) : "f"(r));
}

#define MMA_TF32(d, a, b)                                                        \
    asm("mma.sync.aligned.m16n8k8.row.col.f32.tf32.tf32.f32 "                    \
        "{%0,%1,%2,%3},{%4,%5,%6,%7},{%8,%9},{%0,%1,%2,%3};"                     \
        : "+f"((d)[0]), "+f"((d)[1]), "+f"((d)[2]), "+f"((d)[3])                 \
        : "r"((a)[0]), "r"((a)[1]), "r"((a)[2]), "r"((a)[3]),                    \
          "r"((b)[0]), "r"((b)[1]))

// ---------------- fused tensor-core MLP ----------------------------------------
#define XS  132
#define WS  264
#define HS  260
#define W2S 24
#define SMEM_FLOATS (16896 + 6144)

__global__ __launch_bounds__(256) void mlp_tc_kernel(
    const float* __restrict__ x,
    const float* __restrict__ W1, const float* __restrict__ b1,
    const float* __restrict__ W2, const float* __restrict__ b2)
{
    extern __shared__ float sm[];
    float* xs  = sm;
    float* wsm = sm + 8448;
    float* h1s = sm;
    float* w2s = sm + 16896;

    const int tid  = threadIdx.x;
    const int wid  = tid >> 5;
    const int lane = tid & 31;
    const int g    = lane >> 2;
    const int t    = lane & 3;
    const int n0   = blockIdx.x * 64;

    {
        const float4* xg = (const float4*)(x + (size_t)n0 * INDIM);
        #pragma unroll
        for (int i = 0; i < 8; i++) {
            int lin = i * 256 + tid;
            int row = lin >> 5, c4 = (lin & 31) << 2;
            float4 v = xg[lin];
            *(float4*)(xs + row * XS + c4) = v;
        }
        const float4* wg = (const float4*)W2;
        #pragma unroll
        for (int i = 0; i < 4; i++) {
            int lin = i * 256 + tid;
            int row = lin >> 2, c4 = (lin & 3) << 2;
            float4 v = wg[lin];
            *(float4*)(w2s + row * W2S + c4) = v;
        }
    }

    const int wm = wid >> 2;
    const int wn = wid & 3;
    float acc[2][8][4];
    #pragma unroll
    for (int mt = 0; mt < 2; mt++)
        #pragma unroll
        for (int nt = 0; nt < 8; nt++)
            #pragma unroll
            for (int r = 0; r < 4; r++) acc[mt][nt][r] = 0.f;

    for (int k0 = 0; k0 < INDIM; k0 += 32) {
        __syncthreads();
        {
            const float4* wg = (const float4*)(W1 + (size_t)k0 * H1);
            #pragma unroll
            for (int i = 0; i < 8; i++) {
                int lin = i * 256 + tid;
                int row = lin >> 6, c4 = (lin & 63) << 2;
                float4 v = wg[lin];
                *(float4*)(wsm + row * WS + c4) = v;
            }
        }
        __syncthreads();

        #pragma unroll
        for (int ks = 0; ks < 32; ks += 8) {
            unsigned ahi[2][4], alo[2][4];
            #pragma unroll
            for (int mt = 0; mt < 2; mt++) {
                int rb = wm * 32 + mt * 16;
                float a0 = xs[(rb + g)     * XS + k0 + ks + t];
                float a1 = xs[(rb + g + 8) * XS + k0 + ks + t];
                float a2 = xs[(rb + g)     * XS + k0 + ks + t + 4];
                float a3 = xs[(rb + g + 8) * XS + k0 + ks + t + 4];
                split_tf32(a0, ahi[mt][0], alo[mt][0]);
                split_tf32(a1, ahi[mt][1], alo[mt][1]);
                split_tf32(a2, ahi[mt][2], alo[mt][2]);
                split_tf32(a3, ahi[mt][3], alo[mt][3]);
            }
            #pragma unroll
            for (int nt = 0; nt < 8; nt++) {
                int cb = wn * 64 + nt * 8;
                float b0f = wsm[(ks + t)     * WS + cb + g];
                float b1f = wsm[(ks + t + 4) * WS + cb + g];
                unsigned bhi[2], blo[2];
                split_tf32(b0f, bhi[0], blo[0]);
                split_tf32(b1f, bhi[1], blo[1]);
                #pragma unroll
                for (int mt = 0; mt < 2; mt++) {
                    MMA_TF32(acc[mt][nt], ahi[mt], bhi);
                    MMA_TF32(acc[mt][nt], ahi[mt], blo);
                    MMA_TF32(acc[mt][nt], alo[mt], bhi);
                }
            }
        }
    }
    __syncthreads();

    #pragma unroll
    for (int mt = 0; mt < 2; mt++) {
        int rb = wm * 32 + mt * 16;
        #pragma unroll
        for (int nt = 0; nt < 8; nt++) {
            int cb = wn * 64 + nt * 8 + t * 2;
            float bb0 = b1[cb], bb1 = b1[cb + 1];
            h1s[(rb + g)     * HS + cb    ] = lrelu(acc[mt][nt][0] + bb0);
            h1s[(rb + g)     * HS + cb + 1] = lrelu(acc[mt][nt][1] + bb1);
            h1s[(rb + g + 8) * HS + cb    ] = lrelu(acc[mt][nt][2] + bb0);
            h1s[(rb + g + 8) * HS + cb + 1] = lrelu(acc[mt][nt][3] + bb1);
        }
    }
    __syncthreads();

    {
        const int mt2 = wid >> 1;
        const int nt2 = wid & 1;
        const int rb  = mt2 * 16;
        const int cb  = nt2 * 8;
        float d[4] = {0.f, 0.f, 0.f, 0.f};

        #pragma unroll 4
        for (int k = 0; k < H1; k += 8) {
            float a0 = h1s[(rb + g)     * HS + k + t];
            float a1 = h1s[(rb + g + 8) * HS + k + t];
            float a2 = h1s[(rb + g)     * HS + k + t + 4];
            float a3 = h1s[(rb + g + 8) * HS + k + t + 4];
            unsigned ahi[4], alo[4];
            split_tf32(a0, ahi[0], alo[0]);
            split_tf32(a1, ahi[1], alo[1]);
            split_tf32(a2, ahi[2], alo[2]);
            split_tf32(a3, ahi[3], alo[3]);
            float b0f = w2s[(k + t)     * W2S + cb + g];
            float b1f = w2s[(k + t + 4) * W2S + cb + g];
            unsigned bhi[2], blo[2];
            split_tf32(b0f, bhi[0], blo[0]);
            split_tf32(b1f, bhi[1], blo[1]);
            MMA_TF32(d, ahi, bhi);
            MMA_TF32(d, ahi, blo);
            MMA_TF32(d, alo, bhi);
        }

        int col = cb + t * 2;
        float bb0 = b2[col], bb1 = b2[col + 1];
        g_h[(size_t)(n0 + rb + g)     * HID + col    ] = lrelu(d[0] + bb0);
        g_h[(size_t)(n0 + rb + g)     * HID + col + 1] = lrelu(d[1] + bb1);
        g_h[(size_t)(n0 + rb + g + 8) * HID + col    ] = lrelu(d[2] + bb0);
        g_h[(size_t)(n0 + rb + g + 8) * HID + col + 1] = lrelu(d[3] + bb1);
    }
}

// ---------------- CSR build --------------------------------------------------
__global__ void zero_cnt_kernel()
{
    int i = blockIdx.x * blockDim.x + threadIdx.x;
    if (i < NNODES) g_cnt[i] = 0;
}

__global__ void deg_count_kernel(const int* __restrict__ dst, int E)
{
    int e = blockIdx.x * blockDim.x + threadIdx.x;
    if (e < E) atomicAdd(&g_cnt[clampN(dst[e])], 1);
}

__global__ __launch_bounds__(256) void scanA_kernel()
{
    __shared__ int s[256];
    int i = blockIdx.x * 256 + threadIdx.x;
    s[threadIdx.x] = (i < NNODES) ? g_cnt[i] : 0;
    __syncthreads();
    for (int o = 128; o > 0; o >>= 1) {
        if (threadIdx.x < o) s[threadIdx.x] += s[threadIdx.x + o];
        __syncthreads();
    }
    if (threadIdx.x == 0) g_bsum[blockIdx.x] = s[0];
}

__global__ __launch_bounds__(1024) void scanB_kernel()
{
    __shared__ int s[1024];
    int tid = threadIdx.x;
    int v = (tid < NB_SCAN) ? g_bsum[tid] : 0;
    s[tid] = v;
    __syncthreads();
    for (int o = 1; o < 1024; o <<= 1) {
        int t = (tid >= o) ? s[tid - o] : 0;
        __syncthreads();
        s[tid] += t;
        __syncthreads();
    }
    if (tid < NB_SCAN) g_boff[tid] = s[tid] - v;   // exclusive
}

__global__ __launch_bounds__(256) void scanC_kernel()
{
    __shared__ int s[256];
    int tid = threadIdx.x;
    int i = blockIdx.x * 256 + tid;
    int c = (i < NNODES) ? g_cnt[i] : 0;
    s[tid] = c;
    __syncthreads();
    for (int o = 1; o < 256; o <<= 1) {
        int t = (tid >= o) ? s[tid - o] : 0;
        __syncthreads();
        s[tid] += t;
        __syncthreads();
    }
    if (i < NNODES) {
        int off = g_boff[blockIdx.x] + s[tid] - c;   // exclusive
        g_off[i] = off;
        g_cur[i] = off;
        g_dinv[i] = rsqrtf((float)(c + 1));          // +1 self loop
    }
}

__global__ void scatter_kernel(const int* __restrict__ src, const int* __restrict__ dst, int E)
{
    int e = blockIdx.x * blockDim.x + threadIdx.x;
    if (e >= E) return;
    const int s = clampN(src[e]);
    const int d = clampN(dst[e]);
    int pos = atomicAdd(&g_cur[d], 1);
    g_srcs[pos] = s;
}

// ---------------- per-conv: g_hw = ((maybe lrelu)(in) @ cw) * dinv --------------
__global__ __launch_bounds__(256) void conv_pre_kernel(
    int src_sel,
    const float* __restrict__ cw)
{
    __shared__ float ws[HID * HID];
    __shared__ float ht[16 * HID];

    const int tid = threadIdx.x;
    const int n0  = blockIdx.x * 16;

    if (tid < HID * HID) ws[tid] = cw[tid];
    {
        float v;
        if (src_sel == 0) v = g_h[n0 * HID + tid];
        else              v = lrelu(g_agg[n0 * HID + tid]);
        ht[tid] = v;
    }
    __syncthreads();

    const int n = tid >> 4, j = tid & 15;
    float s = 0.f;
    #pragma unroll
    for (int k = 0; k < HID; k++) s += ht[n * HID + k] * ws[k * HID + j];

    const int gn = n0 + n;
    g_hw[gn * HID + j] = s * g_dinv[gn];
}

// ---------------- aggregation: warp per node, gather from CSR -------------------
// agg[n] = cb + dinv[n] * ( sum_{s in srcs(n)} g_hw[s] + g_hw[n] )
// last==0: write g_agg.  last==1: fused final (h=lrelu(agg) -> out tail; out[n]=h.pwsum+pbsum)
__global__ __launch_bounds__(256) void agg_kernel(
    const float* __restrict__ cb,
    const float* __restrict__ pw, const float* __restrict__ pb,
    float* __restrict__ out, long long out_size, int last)
{
    const int wid  = threadIdx.x >> 5;
    const int lane = threadIdx.x & 31;
    const int n    = blockIdx.x * 8 + wid;
    if (n >= NNODES) return;

    const int q  = lane & 3;       // feature quad
    const int es = lane >> 2;      // edge sub-slot 0..7

    const int beg = g_off[n];
    const int end = beg + g_cnt[n];

    float4 acc = make_float4(0.f, 0.f, 0.f, 0.f);

    for (int i = beg; i < end; i += 8) {
        int sl = -1;
        if (lane < 8 && i + lane < end) sl = g_srcs[i + lane];
        int s = __shfl_sync(0xffffffffu, sl, es);
        if (s >= 0) {
            const float4 v = *(const float4*)(g_hw + (size_t)s * HID + q * 4);
            acc.x += v.x; acc.y += v.y; acc.z += v.z; acc.w += v.w;
        }
    }

    #pragma unroll
    for (int o = 16; o >= 4; o >>= 1) {
        acc.x += __shfl_xor_sync(0xffffffffu, acc.x, o);
        acc.y += __shfl_xor_sync(0xffffffffu, acc.y, o);
        acc.z += __shfl_xor_sync(0xffffffffu, acc.z, o);
        acc.w += __shfl_xor_sync(0xffffffffu, acc.w, o);
    }

    if (lane < 4) {
        const float4 hwn = *(const float4*)(g_hw + (size_t)n * HID + q * 4);
        const float  di  = g_dinv[n];
        const float4 cb4 = __ldg((const float4*)cb + q);
        float4 r;
        r.x = cb4.x + di * (acc.x + hwn.x);
        r.y = cb4.y + di * (acc.y + hwn.y);
        r.z = cb4.z + di * (acc.z + hwn.z);
        r.w = cb4.w + di * (acc.w + hwn.w);

        if (!last) {
            *(float4*)(g_agg + (size_t)n * HID + q * 4) = r;
        } else {
            // fused final: h = lrelu(r), out tail write, dot with pwsum
            float4 h4 = make_float4(lrelu(r.x), lrelu(r.y), lrelu(r.z), lrelu(r.w));
            if (out_size >= (long long)NNODES * (1 + HID))
                *(float4*)(out + NNODES + (size_t)n * HID + q * 4) = h4;

            const float4 pwa = __ldg((const float4*)pw + q * 2);
            const float4 pwb = __ldg((const float4*)pw + q * 2 + 1);
            float part = h4.x * (pwa.x + pwa.y) + h4.y * (pwa.z + pwa.w)
                       + h4.z * (pwb.x + pwb.y) + h4.w * (pwb.z + pwb.w);
            part += __shfl_xor_sync(0x0000000fu, part, 1);
            part += __shfl_xor_sync(0x0000000fu, part, 2);
            if (q == 0) out[n] = part + pb[0] + pb[1];
        }
    }
}

// ---------------- launch: fork-join across two streams ---------------------------
extern "C" void kernel_launch(void* const* d_in, const int* in_sizes, int n_in,
                              void* d_out, int out_size)
{
    const float *x = 0, *W1 = 0, *b1 = 0, *W2 = 0, *b2 = 0;
    const float *cw0 = 0, *cb0 = 0, *cw1 = 0, *cb1 = 0, *pw = 0, *pb = 0;
    const void  *edges = 0;
    long long    edge_elems = 0;

    int n256 = 0, n16 = 0;
    for (int i = 0; i < n_in; i++) {
        const long long sz = in_sizes[i];
        const void* p = d_in[i];
        switch (sz) {
            case 25600000LL: x  = (const float*)p; break;
            case 32768LL:    W1 = (const float*)p; break;
            case 4096LL:     W2 = (const float*)p; break;
            case 32LL:       pw = (const float*)p; break;
            case 2LL:        pb = (const float*)p; break;
            case 256LL:
                if      (n256 == 0) b1  = (const float*)p;
                else if (n256 == 1) cw0 = (const float*)p;
                else                cw1 = (const float*)p;
                n256++; break;
            case 16LL:
                if      (n16 == 0) b2  = (const float*)p;
                else if (n16 == 1) cb0 = (const float*)p;
                else               cb1 = (const float*)p;
                n16++; break;
            default:
                if (sz > 1000000LL) { edges = p; edge_elems = sz; }
                break;
        }
    }

    int E = (int)(edge_elems / 2);
    if (E > EMAX) E = EMAX;
    const int* srcp = (const int*)edges;
    const int* dstp = (const int*)edges + E;

    float* out = (float*)d_out;

    const int NB_NODES16 = NNODES / 16;
    const int NB_NODES   = (NNODES + 255) / 256;
    const int NB_EDGES   = (E + 255) / 256;
    const int NB_AGG     = (NNODES + 7) / 8;

    // one-time resources (created on the uncaptured correctness call)
    static int inited = 0;
    static cudaStream_t s2 = 0;
    static cudaEvent_t  evRoot = 0, evScanC = 0, evCsr = 0;
    if (!inited) {
        cudaFuncSetAttribute(mlp_tc_kernel,
                             cudaFuncAttributeMaxDynamicSharedMemorySize,
                             SMEM_FLOATS * 4);
        cudaStreamCreateWithFlags(&s2, cudaStreamNonBlocking);
        cudaEventCreateWithFlags(&evRoot,  cudaEventDisableTiming);
        cudaEventCreateWithFlags(&evScanC, cudaEventDisableTiming);
        cudaEventCreateWithFlags(&evCsr,   cudaEventDisableTiming);
        inited = 1;
    }

    // fork: s2 runs the CSR build while stream0 runs the MLP
    cudaEventRecord(evRoot, 0);
    cudaStreamWaitEvent(s2, evRoot, 0);

    zero_cnt_kernel <<<NB_NODES, 256, 0, s2>>>();
    deg_count_kernel<<<NB_EDGES, 256, 0, s2>>>(dstp, E);
    scanA_kernel    <<<NB_SCAN, 256, 0, s2>>>();
    scanB_kernel    <<<1, 1024, 0, s2>>>();
    scanC_kernel    <<<NB_SCAN, 256, 0, s2>>>();
    cudaEventRecord(evScanC, s2);
    scatter_kernel  <<<NB_EDGES, 256, 0, s2>>>(srcp, dstp, E);
    cudaEventRecord(evCsr, s2);

    mlp_tc_kernel<<<NNODES / 64, 256, SMEM_FLOATS * 4>>>(x, W1, b1, W2, b2);

    // conv_pre0 needs g_h (stream0) + g_dinv (scanC); overlaps scatter
    cudaStreamWaitEvent(0, evScanC, 0);
    conv_pre_kernel<<<NB_NODES16, 256>>>(0, cw0);

    // agg0 additionally needs g_srcs (scatter)
    cudaStreamWaitEvent(0, evCsr, 0);
    agg_kernel<<<NB_AGG, 256>>>(cb0, pw, pb, out, (long long)out_size, 0);

    conv_pre_kernel<<<NB_NODES16, 256>>>(1, cw1);
    agg_kernel<<<NB_AGG, 256>>>(cb1, pw, pb, out, (long long)out_size, 1);
}